// round 1
// baseline (speedup 1.0000x reference)
#include <cuda_runtime.h>
#include <math_constants.h>

#define BATCH 8
#define H 1080
#define W 1920
#define NPIX (H * W)
#define NTOT (BATCH * NPIX)

// Scratch (device globals — no allocations allowed)
__device__ float g_smooth[NTOT];
__device__ float g_mag[NTOT];
__device__ unsigned char g_dir[NTOT];
__device__ unsigned char g_state0[NTOT];
__device__ unsigned char g_state1[NTOT];

// ---------------------------------------------------------------------------
// Pass 1: x/255 -> gaussian 5x5 (zero pad 2)
// ---------------------------------------------------------------------------
__global__ void k_smooth(const float* __restrict__ x, const float* __restrict__ gw) {
    int ix = blockIdx.x * blockDim.x + threadIdx.x;
    int y  = blockIdx.y;
    int b  = blockIdx.z;
    if (ix >= W) return;
    const float* img = x + (size_t)b * NPIX;
    float s = 0.0f;
#pragma unroll
    for (int dy = 0; dy < 5; dy++) {
        int yy = y + dy - 2;
        if ((unsigned)yy >= (unsigned)H) continue;
#pragma unroll
        for (int dx = 0; dx < 5; dx++) {
            int xx = ix + dx - 2;
            if ((unsigned)xx >= (unsigned)W) continue;
            s = fmaf(img[yy * W + xx], gw[dy * 5 + dx], s);
        }
    }
    g_smooth[(size_t)b * NPIX + (size_t)y * W + ix] = s * (1.0f / 255.0f);
}

// ---------------------------------------------------------------------------
// Pass 2: sobel 3x3 (zero pad 1) -> mag, ang, direction class; writes
// mag_out = mag*255 and ang_out = deg((ang+pi)%2pi) % 180 directly.
// Direction class: round(deg/45) mod 8 mod 4  ->  0=H, 1=45(d1), 2=V, 3=135(d2)
// ---------------------------------------------------------------------------
__global__ void k_grad(const float* __restrict__ sx, const float* __restrict__ sy,
                       float* __restrict__ out_mag, float* __restrict__ out_ang) {
    int ix = blockIdx.x * blockDim.x + threadIdx.x;
    int y  = blockIdx.y;
    int b  = blockIdx.z;
    if (ix >= W) return;
    const float* img = g_smooth + (size_t)b * NPIX;
    float gx = 0.0f, gy = 0.0f;
#pragma unroll
    for (int dy = 0; dy < 3; dy++) {
        int yy = y + dy - 1;
        if ((unsigned)yy >= (unsigned)H) continue;
#pragma unroll
        for (int dx = 0; dx < 3; dx++) {
            int xx = ix + dx - 1;
            if ((unsigned)xx >= (unsigned)W) continue;
            float v = img[yy * W + xx];
            gx = fmaf(v, sx[dy * 3 + dx], gx);
            gy = fmaf(v, sy[dy * 3 + dx], gy);
        }
    }
    float mag = sqrtf(gx * gx + gy * gy + 1e-6f);
    float ang = atan2f(gy, gx);

    float v = ang + CUDART_PI_F;                 // [0, 2pi]
    v = fmodf(v, 2.0f * CUDART_PI_F);            // [0, 2pi)
    float deg = v * (180.0f / CUDART_PI_F);
    int r = (int)rintf(deg / 45.0f);             // 0..8, round-half-even like jnp.round
    int cls = (r & 7) & 3;                       // 0=H,1=d1,2=V,3=d2

    size_t idx = (size_t)b * NPIX + (size_t)y * W + ix;
    g_mag[idx] = mag;
    g_dir[idx] = (unsigned char)cls;
    out_mag[idx] = mag * 255.0f;
    out_ang[idx] = fmodf(deg, 180.0f);
}

// ---------------------------------------------------------------------------
// Pass 3: NMS with WRAP-AROUND neighbors (jnp.roll semantics), including the
// reference's class-1 bug (compares against n_up instead of the opposite
// diagonal). Produces 3-state map: 2=strong edge, 1=low, 0=suppressed.
// ---------------------------------------------------------------------------
__global__ void k_nms() {
    int ix = blockIdx.x * blockDim.x + threadIdx.x;
    int y  = blockIdx.y;
    int b  = blockIdx.z;
    if (ix >= W) return;

    int xl = (ix == 0)     ? W - 1 : ix - 1;
    int xr = (ix == W - 1) ? 0     : ix + 1;
    int yu = (y == 0)      ? H - 1 : y - 1;
    int yd = (y == H - 1)  ? 0     : y + 1;

    const float* m = g_mag + (size_t)b * NPIX;
    size_t idx = (size_t)b * NPIX + (size_t)y * W + ix;
    float c = m[(size_t)y * W + ix];
    int cls = g_dir[idx];

    bool keep;
    if (cls == 0) {          // horizontal: right/left
        keep = (c > m[(size_t)y * W + xr]) && (c > m[(size_t)y * W + xl]);
    } else if (cls == 1) {   // 45 deg: down-right (n_d1) and UP (reference bug)
        keep = (c > m[(size_t)yd * W + xr]) && (c > m[(size_t)yu * W + ix]);
    } else if (cls == 2) {   // vertical: down/up
        keep = (c > m[(size_t)yd * W + ix]) && (c > m[(size_t)yu * W + ix]);
    } else {                 // 135 deg: down-left (n_d3) and up-right (n_d4)
        keep = (c > m[(size_t)yd * W + xl]) && (c > m[(size_t)yu * W + xr]);
    }

    float sup = keep ? c : 0.0f;
    const float HIGHT = 150.0f / 255.0f;
    const float LOWT  = 50.0f  / 255.0f;
    unsigned char st = 0;
    if (sup > HIGHT) st = 2;
    else if (sup >= LOWT && sup < HIGHT) st = 1;
    g_state0[idx] = st;
}

// ---------------------------------------------------------------------------
// Hysteresis iteration (zero-padded 3x3, snapshot semantics):
// low pixel (1) becomes edge (2) iff any 3x3 neighbor in the INPUT snapshot
// is an edge.
// ---------------------------------------------------------------------------
__device__ __forceinline__ unsigned char hyst_step(const unsigned char* __restrict__ in,
                                                   int b, int y, int ix) {
    const unsigned char* p = in + (size_t)b * NPIX;
    unsigned char s = p[(size_t)y * W + ix];
    if (s != 1) return s;
#pragma unroll
    for (int dy = -1; dy <= 1; dy++) {
        int yy = y + dy;
        if ((unsigned)yy >= (unsigned)H) continue;
#pragma unroll
        for (int dx = -1; dx <= 1; dx++) {
            int xx = ix + dx;
            if ((unsigned)xx >= (unsigned)W) continue;
            if (p[(size_t)yy * W + xx] == 2) return 2;
        }
    }
    return 1;
}

__global__ void k_hyst1() {
    int ix = blockIdx.x * blockDim.x + threadIdx.x;
    int y  = blockIdx.y;
    int b  = blockIdx.z;
    if (ix >= W) return;
    g_state1[(size_t)b * NPIX + (size_t)y * W + ix] = hyst_step(g_state0, b, y, ix);
}

__global__ void k_hyst2(float* __restrict__ out_edges) {
    int ix = blockIdx.x * blockDim.x + threadIdx.x;
    int y  = blockIdx.y;
    int b  = blockIdx.z;
    if (ix >= W) return;
    unsigned char r = hyst_step(g_state1, b, y, ix);
    out_edges[(size_t)b * NPIX + (size_t)y * W + ix] = (r == 2) ? 255.0f : 0.0f;
}

// ---------------------------------------------------------------------------
// Launch
// ---------------------------------------------------------------------------
extern "C" void kernel_launch(void* const* d_in, const int* in_sizes, int n_in,
                              void* d_out, int out_size) {
    const float* x  = (const float*)d_in[0];
    const float* gw = (const float*)d_in[1];
    const float* sx = (const float*)d_in[2];
    const float* sy = (const float*)d_in[3];
    float* out = (float*)d_out;
    float* out_edges = out;
    float* out_mag   = out + (size_t)NTOT;
    float* out_ang   = out + (size_t)2 * NTOT;

    dim3 blk(128, 1, 1);
    dim3 grd(W / 128, H, BATCH);   // 1920/128 = 15 exact

    k_smooth<<<grd, blk>>>(x, gw);
    k_grad<<<grd, blk>>>(sx, sy, out_mag, out_ang);
    k_nms<<<grd, blk>>>();
    k_hyst1<<<grd, blk>>>();
    k_hyst2<<<grd, blk>>>(out_edges);
}

// round 5
// speedup vs baseline: 2.0337x; 2.0337x over previous
#include <cuda_runtime.h>
#include <math_constants.h>

#define BATCH 8
#define H 1080
#define W 1920
#define NPIX (H * W)
#define NTOT (BATCH * NPIX)

#define BX 128
#define BY 24
#define NTHR 256

// ---- K1 tile dims ----
#define XW (BX + 6)   // 134: x tile (halo 3)
#define XH (BY + 6)   // 30
#define SW (BX + 2)   // 130: smoothed tile (halo 1)
#define SH (BY + 2)   // 26

// ---- K2 tile dims ----
#define MW (BX + 6)   // 134: mag tile (halo 3, wrap)
#define MH (BY + 6)   // 30
#define S0W (BX + 4)  // 132: state after NMS (halo 2)
#define S0H (BY + 4)  // 28
#define S1W (BX + 2)  // 130: state after hyst1 (halo 1)
#define S1H (BY + 2)  // 26

// Scratch (device globals — no allocations allowed)
__device__ float g_mag[NTOT];
__device__ unsigned char g_dir[NTOT];

// ---------------------------------------------------------------------------
// K1: fused  x/255 -> gaussian 5x5 (zero pad) -> sobel 3x3 (zero pad)
//     -> mag, ang, direction class.  Writes out_mag, out_ang, g_mag, g_dir.
// Accumulation order bit-identical to the round-1 passing kernel.
// ---------------------------------------------------------------------------
__global__ __launch_bounds__(NTHR) void k1(const float* __restrict__ x,
                                           float* __restrict__ out_mag,
                                           float* __restrict__ out_ang) {
    __shared__ float s_x[XH][XW];
    __shared__ float s_s[SH][SW];

    const int x0 = blockIdx.x * BX;
    const int y0 = blockIdx.y * BY;
    const int b  = blockIdx.z;
    const float* img = x + (size_t)b * NPIX;
    const int tid = threadIdx.x;

    // Load x tile (halo 3), zero outside image
    for (int i = tid; i < XH * XW; i += NTHR) {
        int r = i / XW, c = i % XW;
        int gy = y0 + r - 3, gx = x0 + c - 3;
        float v = 0.0f;
        if ((unsigned)gy < (unsigned)H && (unsigned)gx < (unsigned)W)
            v = img[gy * W + gx];
        s_x[r][c] = v;
    }
    __syncthreads();

    // Gaussian (5x5, coefficients /159 as fp32 compile-time constants),
    // evaluated for smoothed tile (halo 1). OOB smoothed positions = 0
    // (sobel uses zero padding of the H x W smoothed tensor).
    for (int i = tid; i < SH * SW; i += NTHR) {
        int r = i / SW, c = i % SW;
        int gy = y0 + r - 1, gx = x0 + c - 1;
        float v = 0.0f;
        if ((unsigned)gy < (unsigned)H && (unsigned)gx < (unsigned)W) {
            const float G[25] = {
                2.0f/159.0f, 4.0f/159.0f,  5.0f/159.0f, 4.0f/159.0f, 2.0f/159.0f,
                4.0f/159.0f, 9.0f/159.0f, 12.0f/159.0f, 9.0f/159.0f, 4.0f/159.0f,
                5.0f/159.0f,12.0f/159.0f, 15.0f/159.0f,12.0f/159.0f, 5.0f/159.0f,
                4.0f/159.0f, 9.0f/159.0f, 12.0f/159.0f, 9.0f/159.0f, 4.0f/159.0f,
                2.0f/159.0f, 4.0f/159.0f,  5.0f/159.0f, 4.0f/159.0f, 2.0f/159.0f };
            float s = 0.0f;
#pragma unroll
            for (int dy = 0; dy < 5; dy++)
#pragma unroll
                for (int dx = 0; dx < 5; dx++)
                    s = fmaf(s_x[r + dy][c + dx], G[dy * 5 + dx], s);
            v = s * (1.0f / 255.0f);
        }
        s_s[r][c] = v;
    }
    __syncthreads();

    // Sobel + magnitude + angle per output pixel.
    for (int i = tid; i < BY * BX; i += NTHR) {
        int r = i / BX, c = i % BX;
        int gyy = y0 + r, gxx = x0 + c;

        // center at s_s[r+1][c+1]; zero-coeff taps skipped (fmaf(v,0,a)==a)
        float a00 = s_s[r][c],     a01 = s_s[r][c + 1],     a02 = s_s[r][c + 2];
        float a10 = s_s[r + 1][c],                          a12 = s_s[r + 1][c + 2];
        float a20 = s_s[r + 2][c], a21 = s_s[r + 2][c + 1], a22 = s_s[r + 2][c + 2];

        float gx = 0.0f;
        gx = fmaf(a00, -0.125f, gx);
        gx = fmaf(a02,  0.125f, gx);
        gx = fmaf(a10, -0.25f,  gx);
        gx = fmaf(a12,  0.25f,  gx);
        gx = fmaf(a20, -0.125f, gx);
        gx = fmaf(a22,  0.125f, gx);

        float gy = 0.0f;
        gy = fmaf(a00, -0.125f, gy);
        gy = fmaf(a01, -0.25f,  gy);
        gy = fmaf(a02, -0.125f, gy);
        gy = fmaf(a20,  0.125f, gy);
        gy = fmaf(a21,  0.25f,  gy);
        gy = fmaf(a22,  0.125f, gy);

        float mag = sqrtf(gx * gx + gy * gy + 1e-6f);
        float ang = atan2f(gy, gx);

        float v = ang + CUDART_PI_F;                 // [0, 2*pi_f]
        const float TWOPI = 2.0f * CUDART_PI_F;
        if (v >= TWOPI) v -= TWOPI;                  // exact == fmodf(v, 2pi)
        float deg = v * (180.0f / CUDART_PI_F);
        int rr = (int)rintf(deg / 45.0f);            // round-half-even == jnp.round
        int cls = (rr & 7) & 3;                      // 0=H, 1=d1(45), 2=V, 3=d2(135)

        float adeg = deg;                            // exact == fmodf(deg, 180)
        if (adeg >= 180.0f) adeg -= 180.0f;
        if (adeg >= 180.0f) adeg -= 180.0f;

        size_t idx = (size_t)b * NPIX + (size_t)gyy * W + gxx;
        g_mag[idx]   = mag;
        g_dir[idx]   = (unsigned char)cls;
        out_mag[idx] = mag * 255.0f;
        out_ang[idx] = adeg;
    }
}

// ---------------------------------------------------------------------------
// K2: fused NMS (wrap-around neighbors, incl. reference's class-1 n_up bug)
//     + 2 hysteresis iterations (zero pad, snapshot semantics) -> edges.
// ---------------------------------------------------------------------------
__global__ __launch_bounds__(NTHR) void k2(float* __restrict__ out_edges) {
    __shared__ float s_m[MH][MW];
    __shared__ unsigned char s_d[S0H][S0W];
    __shared__ unsigned char s_0[S0H][S0W];
    __shared__ unsigned char s_1[S1H][S1W];

    const int x0 = blockIdx.x * BX;
    const int y0 = blockIdx.y * BY;
    const int b  = blockIdx.z;
    const float* m = g_mag + (size_t)b * NPIX;
    const unsigned char* d = g_dir + (size_t)b * NPIX;
    const int tid = threadIdx.x;

    // mag tile (halo 3) with wrap-around (jnp.roll semantics)
    for (int i = tid; i < MH * MW; i += NTHR) {
        int r = i / MW, c = i % MW;
        int gy = y0 + r - 3, gx = x0 + c - 3;
        gy = (gy < 0) ? gy + H : ((gy >= H) ? gy - H : gy);
        gx = (gx < 0) ? gx + W : ((gx >= W) ? gx - W : gx);
        s_m[r][c] = m[gy * W + gx];
    }
    // dir tile (halo 2), only in-image cells matter
    for (int i = tid; i < S0H * S0W; i += NTHR) {
        int r = i / S0W, c = i % S0W;
        int gy = y0 + r - 2, gx = x0 + c - 2;
        unsigned char dv = 0;
        if ((unsigned)gy < (unsigned)H && (unsigned)gx < (unsigned)W)
            dv = d[gy * W + gx];
        s_d[r][c] = dv;
    }
    __syncthreads();

    // NMS + double threshold -> 3-state map (2=edge, 1=low, 0=none),
    // halo-2 region; cells outside image = 0 (zero pad for hysteresis).
    const float HIGHT = 150.0f / 255.0f;
    const float LOWT  = 50.0f  / 255.0f;
    for (int i = tid; i < S0H * S0W; i += NTHR) {
        int r = i / S0W, c = i % S0W;
        int gy = y0 + r - 2, gx = x0 + c - 2;
        unsigned char st = 0;
        if ((unsigned)gy < (unsigned)H && (unsigned)gx < (unsigned)W) {
            float cm = s_m[r + 1][c + 1];
            int cls = s_d[r][c];
            bool keep;
            if (cls == 0)       // horizontal: right/left
                keep = (cm > s_m[r + 1][c + 2]) && (cm > s_m[r + 1][c]);
            else if (cls == 1)  // 45 deg: down-right (n_d1) and UP (ref bug)
                keep = (cm > s_m[r + 2][c + 2]) && (cm > s_m[r][c + 1]);
            else if (cls == 2)  // vertical: down/up
                keep = (cm > s_m[r + 2][c + 1]) && (cm > s_m[r][c + 1]);
            else                // 135 deg: down-left (n_d3), up-right (n_d4)
                keep = (cm > s_m[r + 2][c]) && (cm > s_m[r][c + 2]);
            float sup = keep ? cm : 0.0f;
            if (sup > HIGHT) st = 2;
            else if (sup >= LOWT) st = 1;
        }
        s_0[r][c] = st;
    }
    __syncthreads();

    // Hysteresis iteration 1 (snapshot): low -> edge iff any 3x3 neighbor edge
    for (int i = tid; i < S1H * S1W; i += NTHR) {
        int r = i / S1W, c = i % S1W;
        unsigned char s = s_0[r + 1][c + 1];
        if (s == 1) {
            unsigned char mx = 0;
#pragma unroll
            for (int dy = 0; dy < 3; dy++)
#pragma unroll
                for (int dx = 0; dx < 3; dx++)
                    mx = max(mx, s_0[r + dy][c + dx]);
            if (mx == 2) s = 2;
        }
        s_1[r][c] = s;
    }
    __syncthreads();

    // Hysteresis iteration 2 + final edges write
    for (int i = tid; i < BY * BX; i += NTHR) {
        int r = i / BX, c = i % BX;
        unsigned char s = s_1[r + 1][c + 1];
        if (s == 1) {
            unsigned char mx = 0;
#pragma unroll
            for (int dy = 0; dy < 3; dy++)
#pragma unroll
                for (int dx = 0; dx < 3; dx++)
                    mx = max(mx, s_1[r + dy][c + dx]);
            if (mx == 2) s = 2;
        }
        size_t idx = (size_t)b * NPIX + (size_t)(y0 + r) * W + (x0 + c);
        out_edges[idx] = (s == 2) ? 255.0f : 0.0f;
    }
}

// ---------------------------------------------------------------------------
// Launch
// ---------------------------------------------------------------------------
extern "C" void kernel_launch(void* const* d_in, const int* in_sizes, int n_in,
                              void* d_out, int out_size) {
    const float* x = (const float*)d_in[0];
    float* out = (float*)d_out;
    float* out_edges = out;
    float* out_mag   = out + (size_t)NTOT;
    float* out_ang   = out + (size_t)2 * NTOT;

    dim3 blk(NTHR, 1, 1);
    dim3 grd(W / BX, H / BY, BATCH);   // 15 x 45 x 8

    k1<<<grd, blk>>>(x, out_mag, out_ang);
    k2<<<grd, blk>>>(out_edges);
}

// round 10
// speedup vs baseline: 2.8309x; 1.3920x over previous
#include <cuda_runtime.h>
#include <math_constants.h>

#define BATCH 8
#define H 1080
#define W 1920
#define NPIX (H * W)
#define NTOT (BATCH * NPIX)

#define BX 128
#define BY 24
#define NTHR 256

// ---- K1 tiles (float4 words) ----
#define XROWS (BY + 6)   // 30 ; x col c stored at float idx c+4, c in [-4,139]
#define XW4   36         // 144 floats
#define SROWS (BY + 2)   // 26 ; smoothed col cs at float idx cs+1
#define SW4   34         // 136 floats

// ---- K2 tiles ----
#define MROWS (BY + 6)   // 30 ; mag col c at float idx c+8, c in [-8,135]
#define MW4   36         // 144 floats
#define DROWS (BY + 4)   // 28 ; byte tiles: col c at byte idx c+8
#define BW4   36         // 144 bytes = 36 words
#define S1ROWS (BY + 2)  // 26

// Scratch (device globals — no allocations allowed)
__device__ float g_mag[NTOT];
__device__ unsigned char g_dir[NTOT];

// ---------------------------------------------------------------------------
// K1: fused x/255 -> gaussian 5x5 (zero pad) -> sobel (zero pad) -> mag/ang/cls
// Per-pixel FP accumulation order identical to the round-5 passing kernel.
// ---------------------------------------------------------------------------
__global__ __launch_bounds__(NTHR) void k1(const float* __restrict__ x,
                                           float* __restrict__ out_mag,
                                           float* __restrict__ out_ang) {
    __shared__ float4 s_x[XROWS][XW4];
    __shared__ float4 s_s[SROWS][SW4];

    const int x0 = blockIdx.x * BX, y0 = blockIdx.y * BY, b = blockIdx.z;
    const int tid = threadIdx.x;
    const float* img = x + (size_t)b * NPIX;

    // ---- Phase A: load x tile (halo, zero outside image), vectorized ----
    for (int g = tid; g < XROWS * XW4; g += NTHR) {
        int r = g / XW4, j = g - r * XW4;
        int gy = y0 + r - 3;
        int gx = x0 + 4 * j - 4;
        float4 v = make_float4(0.f, 0.f, 0.f, 0.f);
        if ((unsigned)gy < (unsigned)H) {
            const float* row = img + (size_t)gy * W;
            if (gx >= 0 && gx + 3 < W) {
                v = *(const float4*)(row + gx);
            } else {
                float* vp = &v.x;
#pragma unroll
                for (int k = 0; k < 4; k++)
                    if ((unsigned)(gx + k) < (unsigned)W) vp[k] = row[gx + k];
            }
        }
        s_x[r][j] = v;
    }
    __syncthreads();

    // ---- Phase B: gaussian into s_s (4 px per iteration) ----
    for (int g = tid; g < SROWS * 33; g += NTHR) {
        int r = g / 33, gc = g - r * 33;
        int cs = 4 * gc - 1;          // smoothed col group base, cs in [-1,127]
        int gy = y0 + r - 1;
        const float G[25] = {
            2.0f/159.0f, 4.0f/159.0f,  5.0f/159.0f, 4.0f/159.0f, 2.0f/159.0f,
            4.0f/159.0f, 9.0f/159.0f, 12.0f/159.0f, 9.0f/159.0f, 4.0f/159.0f,
            5.0f/159.0f,12.0f/159.0f, 15.0f/159.0f,12.0f/159.0f, 5.0f/159.0f,
            4.0f/159.0f, 9.0f/159.0f, 12.0f/159.0f, 9.0f/159.0f, 4.0f/159.0f,
            2.0f/159.0f, 4.0f/159.0f,  5.0f/159.0f, 4.0f/159.0f, 2.0f/159.0f };
        float res[4] = {0.f, 0.f, 0.f, 0.f};
#pragma unroll
        for (int dy = 0; dy < 5; dy++) {
            __align__(16) float f[12];
            *(float4*)(f + 0) = s_x[r + dy][gc];
            *(float4*)(f + 4) = s_x[r + dy][gc + 1];
            *(float4*)(f + 8) = s_x[r + dy][gc + 2];
            // x col (cs+j-2+dx) is at local idx 1+j+dx  (word base = float idx cs+1)
#pragma unroll
            for (int j = 0; j < 4; j++)
#pragma unroll
                for (int dx = 0; dx < 5; dx++)
                    res[j] = fmaf(f[1 + j + dx], G[dy * 5 + dx], res[j]);
        }
        float4 sv;
        float* sp = &sv.x;
#pragma unroll
        for (int j = 0; j < 4; j++) {
            int gx = x0 + cs + j;
            sp[j] = ((unsigned)gy < (unsigned)H && (unsigned)gx < (unsigned)W)
                    ? res[j] * (1.0f / 255.0f) : 0.0f;
        }
        s_s[r][gc] = sv;
    }
    __syncthreads();

    // ---- Phase C: sobel + mag + angle, 4 px per iteration ----
    for (int g = tid; g < BY * 32; g += NTHR) {
        int r = g >> 5, gc = g & 31;
        int c = 4 * gc;
        __align__(16) float fm[8], f0[8], fp[8];
        *(float4*)(fm)     = s_s[r][gc];     *(float4*)(fm + 4) = s_s[r][gc + 1];
        *(float4*)(f0)     = s_s[r + 1][gc]; *(float4*)(f0 + 4) = s_s[r + 1][gc + 1];
        *(float4*)(fp)     = s_s[r + 2][gc]; *(float4*)(fp + 4) = s_s[r + 2][gc + 1];

        float4 vmag, vmag255, vang;
        unsigned int dirw = 0;
#pragma unroll
        for (int j = 0; j < 4; j++) {
            // smoothed col (c+j-1+d) at local idx j+d  (word base = float idx c)
            float a00 = fm[j], a01 = fm[j + 1], a02 = fm[j + 2];
            float a10 = f0[j],                  a12 = f0[j + 2];
            float a20 = fp[j], a21 = fp[j + 1], a22 = fp[j + 2];

            float gxv = 0.0f;
            gxv = fmaf(a00, -0.125f, gxv);
            gxv = fmaf(a02,  0.125f, gxv);
            gxv = fmaf(a10, -0.25f,  gxv);
            gxv = fmaf(a12,  0.25f,  gxv);
            gxv = fmaf(a20, -0.125f, gxv);
            gxv = fmaf(a22,  0.125f, gxv);

            float gyv = 0.0f;
            gyv = fmaf(a00, -0.125f, gyv);
            gyv = fmaf(a01, -0.25f,  gyv);
            gyv = fmaf(a02, -0.125f, gyv);
            gyv = fmaf(a20,  0.125f, gyv);
            gyv = fmaf(a21,  0.25f,  gyv);
            gyv = fmaf(a22,  0.125f, gyv);

            float mag = sqrtf(gxv * gxv + gyv * gyv + 1e-6f);
            float ang = atan2f(gyv, gxv);

            float v = ang + CUDART_PI_F;
            const float TWOPI = 2.0f * CUDART_PI_F;
            if (v >= TWOPI) v -= TWOPI;
            float deg = v * (180.0f / CUDART_PI_F);
            int rr = (int)rintf(deg / 45.0f);
            int cls = (rr & 7) & 3;

            float adeg = deg;
            if (adeg >= 180.0f) adeg -= 180.0f;
            if (adeg >= 180.0f) adeg -= 180.0f;

            (&vmag.x)[j]    = mag;
            (&vmag255.x)[j] = mag * 255.0f;
            (&vang.x)[j]    = adeg;
            dirw |= (unsigned int)cls << (8 * j);
        }
        size_t base = (size_t)b * NPIX + (size_t)(y0 + r) * W + (x0 + c);
        *(float4*)(g_mag + base)        = vmag;
        *(float4*)(out_mag + base)      = vmag255;
        *(float4*)(out_ang + base)      = vang;
        *(unsigned int*)(g_dir + base)  = dirw;
    }
}

// ---------------------------------------------------------------------------
// K2: NMS (wrap neighbors, incl. ref's class-1 n_up bug) + 2 hysteresis
//     iterations, SIMD-in-word on packed byte states.
// ---------------------------------------------------------------------------
__global__ __launch_bounds__(NTHR) void k2(float* __restrict__ out_edges) {
    __shared__ float4       s_m[MROWS][MW4];
    __shared__ unsigned int s_d[DROWS][BW4];
    __shared__ unsigned int s_0[DROWS][BW4];
    __shared__ unsigned int s_1[S1ROWS][BW4];

    const int x0 = blockIdx.x * BX, y0 = blockIdx.y * BY, b = blockIdx.z;
    const int tid = threadIdx.x;
    const float* m = g_mag + (size_t)b * NPIX;
    const unsigned char* dd = g_dir + (size_t)b * NPIX;

    // ---- A1: mag tile with wrap (jnp.roll semantics) ----
    for (int g = tid; g < MROWS * MW4; g += NTHR) {
        int r = g / MW4, j = g - r * MW4;
        int gy = y0 + r - 3;
        if (gy < 0) gy += H; else if (gy >= H) gy -= H;
        int gx = x0 + 4 * j - 8;
        const float* row = m + (size_t)gy * W;
        float4 v;
        if (gx >= 0 && gx + 3 < W) {
            v = *(const float4*)(row + gx);
        } else {
            float* vp = &v.x;
#pragma unroll
            for (int k = 0; k < 4; k++) {
                int t = gx + k;
                if (t < 0) t += W; else if (t >= W) t -= W;
                vp[k] = row[t];
            }
        }
        s_m[r][j] = v;
    }
    // ---- A2: dir tile (zero outside image) ----
    for (int g = tid; g < DROWS * BW4; g += NTHR) {
        int r = g / BW4, j = g - r * BW4;
        int gy = y0 + r - 2;
        int gx = x0 + 4 * j - 8;
        unsigned int v = 0;
        if ((unsigned)gy < (unsigned)H) {
            const unsigned char* row = dd + (size_t)gy * W;
            if (gx >= 0 && gx + 3 < W) {
                v = *(const unsigned int*)(row + gx);
            } else {
#pragma unroll
                for (int k = 0; k < 4; k++)
                    if ((unsigned)(gx + k) < (unsigned)W)
                        v |= (unsigned int)row[gx + k] << (8 * k);
            }
        }
        s_d[r][j] = v;
    }
    // ---- A3: zero the unwritten edge words of s_0 ----
    for (int g = tid; g < DROWS * 2; g += NTHR)
        s_0[g >> 1][(g & 1) ? 35 : 0] = 0u;
    __syncthreads();

    // ---- B: NMS + double threshold -> packed states (2=edge,1=low,0=none) ----
    const float HIGHT = 150.0f / 255.0f;
    const float LOWT  = 50.0f  / 255.0f;
    for (int g = tid; g < DROWS * 34; g += NTHR) {
        int r = g / 34, gi = g - r * 34;
        int cc = 4 * gi - 4;                 // state col group base in [-4,128]
        int gy = y0 + (r - 2);
        __align__(16) float um[12], cm[12], dm[12];
        *(float4*)(um) = s_m[r][gi];     *(float4*)(um+4) = s_m[r][gi+1];     *(float4*)(um+8) = s_m[r][gi+2];
        *(float4*)(cm) = s_m[r+1][gi];   *(float4*)(cm+4) = s_m[r+1][gi+1];   *(float4*)(cm+8) = s_m[r+1][gi+2];
        *(float4*)(dm) = s_m[r+2][gi];   *(float4*)(dm+4) = s_m[r+2][gi+1];   *(float4*)(dm+8) = s_m[r+2][gi+2];
        unsigned int dw = s_d[r][gi + 1];
        bool rowok = (unsigned)gy < (unsigned)H;
        unsigned int word = 0;
#pragma unroll
        for (int j = 0; j < 4; j++) {
            // mag col (cc+j+d) at local idx j+4+d
            float c0 = cm[j + 4];
            int cls = (int)((dw >> (8 * j)) & 0xFF);
            float n1 = (cls == 0) ? cm[j + 5]             // R
                     : (cls == 1) ? dm[j + 5]             // DR (n_d1)
                     : (cls == 2) ? dm[j + 4]             // D
                                  : dm[j + 3];            // DL (n_d3)
            float n2 = (cls == 0) ? cm[j + 3]             // L
                     : (cls == 3) ? um[j + 5]             // UR (n_d4)
                                  : um[j + 4];            // U (cls 1 ref-bug & cls 2)
            int st = 0;
            if ((c0 > n1) && (c0 > n2))
                st = (c0 > HIGHT) ? 2 : ((c0 >= LOWT) ? 1 : 0);
            int gx = x0 + cc + j;
            if (!(rowok && (unsigned)gx < (unsigned)W)) st = 0;
            word |= (unsigned int)st << (8 * j);
        }
        s_0[r][gi + 1] = word;
    }
    __syncthreads();

    // ---- C: hysteresis iter 1 (snapshot, zero pad), SIMD bytes ----
    for (int g = tid; g < S1ROWS * 34; g += NTHR) {
        int r = g / 34, gi = g - r * 34;
        unsigned int mx = 0, ctr = 0;
#pragma unroll
        for (int q = 0; q < 3; q++) {
            unsigned int p = s_0[r + q][gi], c = s_0[r + q][gi + 1], n = s_0[r + q][gi + 2];
            unsigned int lft = __byte_perm(p, c, 0x6543);
            unsigned int rgt = __byte_perm(c, n, 0x4321);
            mx = __vmaxu4(mx, __vmaxu4(lft, __vmaxu4(c, rgt)));
            if (q == 1) ctr = c;
        }
        unsigned int is1 = __vcmpeq4(ctr, 0x01010101u);
        unsigned int nb2 = __vcmpeq4(mx, 0x02020202u);
        s_1[r][gi + 1] = ctr + (is1 & nb2 & 0x01010101u);
    }
    __syncthreads();

    // ---- D: hysteresis iter 2 + edges output (float4 stores) ----
    for (int g = tid; g < BY * 32; g += NTHR) {
        int r = g >> 5, gi = g & 31;
        int cc = 4 * gi;
        unsigned int mx = 0, ctr = 0;
#pragma unroll
        for (int q = 0; q < 3; q++) {
            unsigned int p = s_1[r + q][gi + 1], c = s_1[r + q][gi + 2], n = s_1[r + q][gi + 3];
            unsigned int lft = __byte_perm(p, c, 0x6543);
            unsigned int rgt = __byte_perm(c, n, 0x4321);
            mx = __vmaxu4(mx, __vmaxu4(lft, __vmaxu4(c, rgt)));
            if (q == 1) ctr = c;
        }
        unsigned int is1 = __vcmpeq4(ctr, 0x01010101u);
        unsigned int nb2 = __vcmpeq4(mx, 0x02020202u);
        unsigned int res = ctr + (is1 & nb2 & 0x01010101u);

        float4 o;
        float* op = &o.x;
#pragma unroll
        for (int j = 0; j < 4; j++)
            op[j] = (((res >> (8 * j)) & 0xFF) == 2u) ? 255.0f : 0.0f;
        size_t base = (size_t)b * NPIX + (size_t)(y0 + r) * W + (x0 + cc);
        *(float4*)(out_edges + base) = o;
    }
}

// ---------------------------------------------------------------------------
// Launch
// ---------------------------------------------------------------------------
extern "C" void kernel_launch(void* const* d_in, const int* in_sizes, int n_in,
                              void* d_out, int out_size) {
    const float* x = (const float*)d_in[0];
    float* out = (float*)d_out;
    float* out_edges = out;
    float* out_mag   = out + (size_t)NTOT;
    float* out_ang   = out + (size_t)2 * NTOT;

    dim3 blk(NTHR, 1, 1);
    dim3 grd(W / BX, H / BY, BATCH);   // 15 x 45 x 8

    k1<<<grd, blk>>>(x, out_mag, out_ang);
    k2<<<grd, blk>>>(out_edges);
}